// round 7
// baseline (speedup 1.0000x reference)
#include <cuda_runtime.h>
#include <cstdint>

// Problem constants:
// B=32, N=32, P0=16, P1=32, P2=16, R=3, D=8, V=2
// num_in = 112, RD = 24
// out per b: 16 (null) + 1024 (unary) + 32*31*16 (binary) = 16912

#define RD 24
#define NUMIN 112

typedef unsigned long long u64;

// -------- device scratch --------
__device__ float g_BW[384 * 4];            // packed binary weights [kk][rdp]:(w0,w1,c0,c1)
__device__ float g_PU1T[32 * 32 * 24];     // [b][i][rd]  PN*U1*sigmoid(or)
__device__ float g_U2T[32 * 32 * 24];      // [b][j][rd]  U2
__device__ float g_part0[32 * 32];         // per (b,i): prod_jj (1 - dis0)
__device__ unsigned int g_ctr = 0;

// -------- packed f32x2 helpers (Blackwell) --------
__device__ __forceinline__ u64 pk2(float a, float b) {
    u64 r; asm("mov.b64 %0, {%1,%2};" : "=l"(r) : "f"(a), "f"(b)); return r;
}
__device__ __forceinline__ void upk2(u64 v, float& a, float& b) {
    asm("mov.b64 {%0,%1}, %2;" : "=f"(a), "=f"(b) : "l"(v));
}
__device__ __forceinline__ u64 fma2(u64 a, u64 b, u64 c) {
    u64 d; asm("fma.rn.f32x2 %0, %1, %2, %3;" : "=l"(d) : "l"(a), "l"(b), "l"(c)); return d;
}
__device__ __forceinline__ u64 mul2(u64 a, u64 b) {
    u64 d; asm("mul.rn.f32x2 %0, %1, %2;" : "=l"(d) : "l"(a), "l"(b)); return d;
}
__device__ __forceinline__ void lds_wc(u64& w, u64& c, uint32_t addr) {
    asm volatile("ld.shared.v2.u64 {%0,%1}, [%2];" : "=l"(w), "=l"(c) : "r"(addr));
}
__device__ __forceinline__ uint32_t smem_u32(const void* p) {
    uint32_t a;
    asm("{ .reg .u64 t; cvta.to.shared.u64 t, %1; cvt.u32.u64 %0, t; }" : "=r"(a) : "l"(p));
    return a;
}

// ============================================================================
// k1: weights + per-(b,obj) partial products.
// grid = (32 b, 2 h), block = 384. Each block handles rd in [h*12, h*12+12).
// Thread t: obj = t&31, rdl = t>>5 -> one U2 item + one PU1 item.
// (b==0) blocks publish their half of the packed binary weight table.
// ============================================================================
__global__ __launch_bounds__(384, 1)
void k1(const float* __restrict__ nul, const float* __restrict__ una,
        const float* __restrict__ andk, const float* __restrict__ ork) {
    __shared__ float2 sWC[12 * NUMIN];   // local (w,c) for this block's 12 rd
    __shared__ float  sU[32 * 32];       // [k][i] transposed
    __shared__ float  sN[16];
    __shared__ float  sOK[12];

    const int b = blockIdx.x;
    const int h = blockIdx.y;            // 0 or 1: rd base = h*12
    const int t = threadIdx.x;

    // softmax for this block's 12 rd (1344 items), fast math
    for (int l = t; l < 12 * NUMIN; l += 384) {
        int gidx = h * (12 * NUMIN) + l;
        float a0 = andk[gidx * 3 + 0];
        float a1 = andk[gidx * 3 + 1];
        float a2 = andk[gidx * 3 + 2];
        float e0 = __expf(a0), e1 = __expf(a1), e2 = __expf(a2);
        float inv = __fdividef(1.0f, e0 + e1 + e2);
        sWC[l] = make_float2((e0 - e1) * inv, (e1 + e2) * inv);
    }
    for (int idx = t; idx < 1024; idx += 384) {
        int ii = idx >> 5, k = idx & 31;
        sU[k * 32 + ii] = una[b * 1024 + idx];
    }
    if (t < 16) sN[t] = nul[b * 16 + t];
    else if (t >= 32 && t < 44) {
        float x = ork[h * 12 + (t - 32)];
        sOK[t - 32] = __fdividef(1.0f, 1.0f + __expf(-x));
    }
    __syncthreads();

    // publish packed binary weights (b==0 blocks; each h does its 6 rdp columns)
    if (b == 0 && t < 192) {
        int kk = t / 6, rdpl = t % 6;
        int slice = (kk < 16) ? (80 + kk) : (96 + kk - 16);
        float2 lo = sWC[(2 * rdpl)     * NUMIN + slice];
        float2 hi = sWC[(2 * rdpl + 1) * NUMIN + slice];
        ((float4*)g_BW)[kk * 12 + h * 6 + rdpl] = make_float4(lo.x, hi.x, lo.y, hi.y);
    }

    const int obj = t & 31;       // i or j
    const int rdl = t >> 5;       // 0..11
    const int rd  = h * 12 + rdl;

    // U2[b][obj][rd], 4-way split chain
    {
        const float2* wc = sWC + rdl * NUMIN + 48;
        float pa = 1.0f, pb = 1.0f, pc = 1.0f, pd = 1.0f;
#pragma unroll
        for (int k = 0; k < 8; k++) {
            float2 w0 = wc[k],      w1 = wc[8 + k];
            float2 w2 = wc[16 + k], w3 = wc[24 + k];
            pa *= fmaf(sU[k * 32 + obj],        w0.x, w0.y);
            pb *= fmaf(sU[(8 + k) * 32 + obj],  w1.x, w1.y);
            pc *= fmaf(sU[(16 + k) * 32 + obj], w2.x, w2.y);
            pd *= fmaf(sU[(24 + k) * 32 + obj], w3.x, w3.y);
        }
        g_U2T[(b * 32 + obj) * 24 + rd] = (pa * pb) * (pc * pd);
    }
    // PU1[b][obj][rd] = PN * U1 * sigmoid(or)
    {
        const float2* wc = sWC + rdl * NUMIN;
        float pa = 1.0f, pb = 1.0f, pc = 1.0f, pd = 1.0f;
#pragma unroll
        for (int k = 0; k < 8; k++) {
            float2 w0 = wc[k], w1 = wc[8 + k];
            pa *= fmaf(sN[k],     w0.x, w0.y);
            pb *= fmaf(sN[8 + k], w1.x, w1.y);
        }
#pragma unroll
        for (int k = 0; k < 16; k++) {
            float2 w0 = wc[16 + k], w1 = wc[32 + k];
            pc *= fmaf(sU[k * 32 + obj],        w0.x, w0.y);
            pd *= fmaf(sU[(16 + k) * 32 + obj], w1.x, w1.y);
        }
        g_PU1T[(b * 32 + obj) * 24 + rd] = ((pa * pb) * (pc * pd)) * sOK[rdl];
    }
}

// ============================================================================
// k2: hot kernel. grid = (32 i, 32 b), block = 32 (one warp, lane = jj).
// Full 32-kk conjunct loop per thread. Prologue = pure loads.
// Last-block ticket writes the nullary outputs.
// ============================================================================
__global__ __launch_bounds__(32)
void k2(const float* __restrict__ nul, const float* __restrict__ una,
        const float* __restrict__ binp, float* __restrict__ out) {
    __shared__ float4 sBW[384];   // [kk][rdp] : (w0,w1,c0,c1)
    __shared__ int    sIsLast;

    const int i = blockIdx.x;
    const int b = blockIdx.y;
    const int lane = threadIdx.x;

    const int  jj     = lane;
    const bool active = (jj < 31);
    const int  jj_s   = active ? jj : 0;
    const int  j      = jj_s + (jj_s >= i);     // second object index
    const int  ip     = i - (jj_s < i);         // binary col index for (j,i)

    // fill shared weights (6 KB), 12 float4 per lane
    const float4* gbw = (const float4*)g_BW;
#pragma unroll
    for (int q = 0; q < 12; q++) sBW[lane + q * 32] = gbw[lane + q * 32];

    // load 32 x values: x1 = binp[b,i,jj,0..15], x2 = binp[b,j,ip,0..15]
    float xs[32];
    {
        const float4* p1 = (const float4*)(binp + (((size_t)b * 32 + i) * 31 + jj_s) * 16);
        const float4* p2 = (const float4*)(binp + (((size_t)b * 32 + j) * 31 + ip)  * 16);
        float4 va[4], vb[4];
#pragma unroll
        for (int q = 0; q < 4; q++) va[q] = p1[q];
#pragma unroll
        for (int q = 0; q < 4; q++) vb[q] = p2[q];
#pragma unroll
        for (int q = 0; q < 4; q++) {
            xs[4 * q + 0] = va[q].x; xs[4 * q + 1] = va[q].y;
            xs[4 * q + 2] = va[q].z; xs[4 * q + 3] = va[q].w;
            xs[16 + 4 * q + 0] = vb[q].x; xs[16 + 4 * q + 1] = vb[q].y;
            xs[16 + 4 * q + 2] = vb[q].z; xs[16 + 4 * q + 3] = vb[q].w;
        }
    }
    const float uk = una[(size_t)b * 1024 + i * 32 + lane];

    // acc init: PU1[b][i][rd] (broadcast) * U2[b][j][rd] (per-lane), float4 loads
    u64 acc[12];
    {
        const float4* puv = (const float4*)(g_PU1T + ((size_t)b * 32 + i) * 24);
        const float4* u2v = (const float4*)(g_U2T  + ((size_t)b * 32 + j) * 24);
        float4 pu[6], u2[6];
#pragma unroll
        for (int q = 0; q < 6; q++) pu[q] = puv[q];
#pragma unroll
        for (int q = 0; q < 6; q++) u2[q] = u2v[q];
#pragma unroll
        for (int q = 0; q < 6; q++) {
            acc[2 * q]     = pk2(pu[q].x * u2[q].x, pu[q].y * u2[q].y);
            acc[2 * q + 1] = pk2(pu[q].z * u2[q].z, pu[q].w * u2[q].w);
        }
    }

    __syncwarp();   // sBW visible to all lanes

    const uint32_t sb = smem_u32(sBW);
#pragma unroll
    for (int kk = 0; kk < 32; kk++) {
        u64 xx = pk2(xs[kk], xs[kk]);
#pragma unroll
        for (int rdp = 0; rdp < 12; rdp++) {
            u64 w, c;
            lds_wc(w, c, sb + (uint32_t)((kk * 12 + rdp) * 16));
            acc[rdp] = mul2(acc[rdp], fma2(xx, w, c));
        }
    }

    // tv[rd] = 1 - conj*ok ; rule products over D=8
    float tv[24];
#pragma unroll
    for (int rdp = 0; rdp < 12; rdp++) {
        float lo, hi;
        upk2(acc[rdp], lo, hi);
        tv[2 * rdp]     = 1.0f - lo;
        tv[2 * rdp + 1] = 1.0f - hi;
    }
    float pr0 = 1.0f, pr1 = 1.0f, pr2 = 1.0f;
#pragma unroll
    for (int d = 0; d < 8; d++) {
        pr0 *= tv[d];
        pr1 *= tv[8 + d];
        pr2 *= tv[16 + d];
    }

    // binary output row: copy channels 0..14, merge channel 15
    if (active) {
        float4 o[4];
#pragma unroll
        for (int q = 0; q < 4; q++) {
            o[q].x = xs[4 * q + 0]; o[q].y = xs[4 * q + 1];
            o[q].z = xs[4 * q + 2]; o[q].w = xs[4 * q + 3];
        }
        o[3].w = 1.0f - (1.0f - xs[15]) * pr2;
        float4* ob = (float4*)(out + (size_t)b * 16912 + 1040 + (size_t)(i * 31 + jj) * 16);
#pragma unroll
        for (int q = 0; q < 4; q++) ob[q] = o[q];
    } else {
        pr0 = 1.0f;
        pr1 = 1.0f;
    }

    // warp product-reductions over jj
    float r0 = pr0, r1 = pr1;
#pragma unroll
    for (int s = 16; s > 0; s >>= 1) {
        r0 *= __shfl_xor_sync(0xFFFFFFFFu, r0, s);
        r1 *= __shfl_xor_sync(0xFFFFFFFFu, r1, s);
    }

    // unary output row
    {
        float uv = (lane < 31) ? uk : (1.0f - (1.0f - uk) * r1);
        out[(size_t)b * 16912 + 16 + i * 32 + lane] = uv;
    }

    // ---- last-block nullary epilogue (ticket over 1024 blocks) ----
    if (lane == 0) {
        __stcg(&g_part0[b * 32 + i], r0);
        __threadfence();
        unsigned int ticket = atomicAdd(&g_ctr, 1u);
        sIsLast = (ticket == 1023u) ? 1 : 0;
    }
    __syncwarp();

    if (sIsLast) {
        __threadfence();
        // channels 0..14: plain copy
        for (int item = lane; item < 512; item += 32) {
            int bb = item >> 4, c = item & 15;
            if (c < 15) out[(size_t)bb * 16912 + c] = nul[bb * 16 + c];
        }
        // channel 15: thread 'lane' handles bb = lane
        {
            int bb = lane;
            const float4* pp = (const float4*)(g_part0 + bb * 32);
            float p = 1.0f;
#pragma unroll
            for (int q = 0; q < 8; q++) {
                float4 v = __ldcg((float4*)(pp + q));
                p *= (v.x * v.y) * (v.z * v.w);
            }
            float v = nul[bb * 16 + 15];
            out[(size_t)bb * 16912 + 15] = 1.0f - (1.0f - v) * p;
        }
        if (lane == 0) atomicExch(&g_ctr, 0u);
    }
}

// ============================================================================
extern "C" void kernel_launch(void* const* d_in, const int* in_sizes, int n_in,
                              void* d_out, int out_size) {
    // Identify the 5 inputs by rank order of element count (all distinct):
    //   ork (24) < nul (512) < andk (8064) < una (32768) < binp (507904)
    int order[5] = {0, 1, 2, 3, 4};
    for (int a = 1; a < 5 && a < n_in; a++) {
        int key = order[a];
        int ks = in_sizes[key];
        int bpos = a - 1;
        while (bpos >= 0 && in_sizes[order[bpos]] > ks) {
            order[bpos + 1] = order[bpos];
            bpos--;
        }
        order[bpos + 1] = key;
    }
    const float* ork  = (const float*)d_in[order[0]];
    const float* nul  = (const float*)d_in[order[1]];
    const float* andk = (const float*)d_in[order[2]];
    const float* una  = (const float*)d_in[order[3]];
    const float* binp = (const float*)d_in[order[4]];
    float* out = (float*)d_out;

    k1<<<dim3(32, 2), 384>>>(nul, una, andk, ork);
    k2<<<dim3(32, 32), 32>>>(nul, una, binp, out);
}

// round 9
// speedup vs baseline: 1.0233x; 1.0233x over previous
#include <cuda_runtime.h>
#include <cstdint>

// Problem constants:
// B=32, N=32, P0=16, P1=32, P2=16, R=3, D=8, V=2
// num_in = 112, RD = 24
// out per b: 16 (null) + 1024 (unary) + 32*31*16 (binary) = 16912

#define RD 24
#define NUMIN 112

typedef unsigned long long u64;

// -------- device scratch --------
__device__ float g_BW[384 * 4];            // packed binary weights [kk][rdp]:(w0,w1,c0,c1)
__device__ float g_PU1[32 * RD * 32];      // [b][rd][i]  PN*U1*sigmoid(or)
__device__ float g_U2[32 * RD * 32];       // [b][rd][j]  U2
__device__ float g_partB[32 * 8];          // per (b, ig) partial nullary product
__device__ unsigned int g_flag[32];        // per-b ready flag
__device__ unsigned int g_ctr = 0;         // main-block ticket counter

// -------- packed f32x2 helpers (Blackwell) --------
__device__ __forceinline__ u64 pk2(float a, float b) {
    u64 r; asm("mov.b64 %0, {%1,%2};" : "=l"(r) : "f"(a), "f"(b)); return r;
}
__device__ __forceinline__ void upk2(u64 v, float& a, float& b) {
    asm("mov.b64 {%0,%1}, %2;" : "=f"(a), "=f"(b) : "l"(v));
}
__device__ __forceinline__ u64 fma2(u64 a, u64 b, u64 c) {
    u64 d; asm("fma.rn.f32x2 %0, %1, %2, %3;" : "=l"(d) : "l"(a), "l"(b), "l"(c)); return d;
}
__device__ __forceinline__ u64 mul2(u64 a, u64 b) {
    u64 d; asm("mul.rn.f32x2 %0, %1, %2;" : "=l"(d) : "l"(a), "l"(b)); return d;
}
__device__ __forceinline__ void lds_wc(u64& w, u64& c, uint32_t addr) {
    asm volatile("ld.shared.v2.u64 {%0,%1}, [%2];" : "=l"(w), "=l"(c) : "r"(addr));
}
__device__ __forceinline__ uint32_t smem_u32(const void* p) {
    uint32_t a;
    asm("{ .reg .u64 t; cvta.to.shared.u64 t, %1; cvt.u32.u64 %0, t; }" : "=r"(a) : "l"(p));
    return a;
}

// Shared-memory union offsets (bytes)
#define SM_BYTES   25792
// main layout
#define OFF_BW     0        // float4[384]  -> 6144
#define OFF_U2     6144     // float[800]   -> 9344  (sU2[j*25+rd])
#define OFF_PU1    9344     // float[96]    -> 9728
#define OFF_ACC    9728     // u64[1536]    -> 22016
#define OFF_R0     22016    // float[4]
#define OFF_LAST   22032    // int
// aux layout
#define OFF_WC     0        // float2[2688] -> 21504
#define OFF_AU     21504    // float[1024]  -> 25600
#define OFF_AN     25600    // float[16]
#define OFF_AOK    25664    // float[24]

// ============================================================================
// One kernel, grid = 288 x 256.
// Blocks 0..31  : aux (producer) for batch b = bid.
// Blocks 32..287: main (consumer): m = bid-32, ig = m&7, b = m>>3.
// ============================================================================
__global__ __launch_bounds__(256, 2)
void kAll(const float* __restrict__ nul, const float* __restrict__ una,
          const float* __restrict__ binp, const float* __restrict__ andk,
          const float* __restrict__ ork, float* __restrict__ out) {
    __shared__ __align__(16) char sm[SM_BYTES];

    const int bid = blockIdx.x;
    const int t   = threadIdx.x;

    if (bid < 32) {
        // ==================== AUX (producer) ====================
        const int b = bid;
        float2* sWC = (float2*)(sm + OFF_WC);
        float*  sU  = (float*)(sm + OFF_AU);
        float*  sN  = (float*)(sm + OFF_AN);
        float*  sOK = (float*)(sm + OFF_AOK);

        // softmax (fast math): 2688 items
        for (int idx = t; idx < RD * NUMIN; idx += 256) {
            float a0 = andk[idx * 3 + 0];
            float a1 = andk[idx * 3 + 1];
            float a2 = andk[idx * 3 + 2];
            float e0 = __expf(a0), e1 = __expf(a1), e2 = __expf(a2);
            float inv = __fdividef(1.0f, e0 + e1 + e2);
            sWC[idx] = make_float2((e0 - e1) * inv, (e1 + e2) * inv);
        }
        for (int idx = t; idx < 1024; idx += 256) {
            int ii = idx >> 5, k = idx & 31;
            sU[k * 32 + ii] = una[b * 1024 + idx];
        }
        if (t < 16) sN[t] = nul[b * 16 + t];
        else if (t >= 32 && t < 56) {
            float x = ork[t - 32];
            sOK[t - 32] = __fdividef(1.0f, 1.0f + __expf(-x));
        }
        __syncthreads();

        // publish packed binary weights — ALL 384 entries (256-thread block!)
        for (int idx = t; idx < 384; idx += 256) {
            int kk = idx / 12, rdp = idx % 12;
            int slice = (kk < 16) ? (80 + kk) : (96 + kk - 16);
            float2 lo = sWC[(2 * rdp)     * NUMIN + slice];
            float2 hi = sWC[(2 * rdp + 1) * NUMIN + slice];
            ((float4*)g_BW)[idx] = make_float4(lo.x, hi.x, lo.y, hi.y);
        }
        // nullary output channels 0..14 (in-range threads!)
        if (t < 15) {
            out[(size_t)b * 16912 + t] = sN[t];
        }

        // 3 (obj, rd) items per thread: U2 + PU1
#pragma unroll
        for (int it = 0; it < 3; it++) {
            int item = t + it * 256;
            int obj = item & 31, rd = item >> 5;
            {
                const float2* wc = sWC + rd * NUMIN + 48;
                float pa = 1.0f, pb = 1.0f, pc = 1.0f, pd = 1.0f;
#pragma unroll
                for (int k = 0; k < 8; k++) {
                    float2 w0 = wc[k],      w1 = wc[8 + k];
                    float2 w2 = wc[16 + k], w3 = wc[24 + k];
                    pa *= fmaf(sU[k * 32 + obj],        w0.x, w0.y);
                    pb *= fmaf(sU[(8 + k) * 32 + obj],  w1.x, w1.y);
                    pc *= fmaf(sU[(16 + k) * 32 + obj], w2.x, w2.y);
                    pd *= fmaf(sU[(24 + k) * 32 + obj], w3.x, w3.y);
                }
                g_U2[b * 768 + rd * 32 + obj] = (pa * pb) * (pc * pd);
            }
            {
                const float2* wc = sWC + rd * NUMIN;
                float pa = 1.0f, pb = 1.0f, pc = 1.0f, pd = 1.0f;
#pragma unroll
                for (int k = 0; k < 8; k++) {
                    float2 w0 = wc[k], w1 = wc[8 + k];
                    pa *= fmaf(sN[k],     w0.x, w0.y);
                    pb *= fmaf(sN[8 + k], w1.x, w1.y);
                }
#pragma unroll
                for (int k = 0; k < 16; k++) {
                    float2 w0 = wc[16 + k], w1 = wc[32 + k];
                    pc *= fmaf(sU[k * 32 + obj],        w0.x, w0.y);
                    pd *= fmaf(sU[(16 + k) * 32 + obj], w1.x, w1.y);
                }
                g_PU1[(b * RD + rd) * 32 + obj] = ((pa * pb) * (pc * pd)) * sOK[rd];
            }
        }

        // release: make all stores visible, then set flag
        __threadfence();
        __syncthreads();
        if (t == 0) atomicExch(&g_flag[b], 1u);
        return;
    }

    // ==================== MAIN (consumer) ====================
    const int m    = bid - 32;
    const int ig   = m & 7;               // 0..7
    const int b    = m >> 3;              // 0..31
    const int wid  = t >> 5;              // 0..7
    const int lane = t & 31;
    const int half  = wid >> 2;           // 0 or 1
    const int i_loc = wid & 3;
    const int i     = ig * 4 + i_loc;

    float4* sBW  = (float4*)(sm + OFF_BW);
    float*  sU2  = (float*)(sm + OFF_U2);
    float*  sPU1 = (float*)(sm + OFF_PU1);
    u64*    sAcc = (u64*)(sm + OFF_ACC);
    float*  sWarpR0 = (float*)(sm + OFF_R0);
    int*    sIsLast = (int*)(sm + OFF_LAST);

    const int  jj     = lane;
    const bool active = (jj < 31);
    const int  jj_s   = active ? jj : 0;
    const int  j      = jj_s + (jj_s >= i);
    const int  ip     = i - (jj_s < i);

    // ---- hoisted global loads (overlap the flag spin) ----
    float xs[16];
    {
        const size_t row = half ? (((size_t)b * 32 + j) * 31 + ip)
                                : (((size_t)b * 32 + i) * 31 + jj_s);
        const float4* p = (const float4*)(binp + row * 16);
        float4 v[4];
#pragma unroll
        for (int q = 0; q < 4; q++) v[q] = p[q];
#pragma unroll
        for (int q = 0; q < 4; q++) {
            xs[4 * q + 0] = v[q].x; xs[4 * q + 1] = v[q].y;
            xs[4 * q + 2] = v[q].z; xs[4 * q + 3] = v[q].w;
        }
    }
    const float uk = (half == 0) ? una[(size_t)b * 1024 + i * 32 + lane] : 0.0f;

    // ---- wait for producer b ----
    if (t == 0) {
        while (atomicAdd(&g_flag[b], 0u) == 0u) __nanosleep(64);
        __threadfence();   // acquire
    }
    __syncthreads();

    // ---- prologue: pure loads into shared (bypass L1 for freshness) ----
    {
        const float4* gbw = (const float4*)g_BW;
        sBW[t]       = __ldcg(gbw + t);
        sBW[t + 128] = __ldcg(gbw + t + 128);
        sBW[t + 256] = __ldcg(gbw + t + 256);
    }
    {
        int item = t;
        int rd = item >> 5, jx = item & 31;
        sU2[jx * 25 + rd] = __ldcg(&g_U2[b * 768 + item]);
        item = t + 256; rd = item >> 5; jx = item & 31;
        sU2[jx * 25 + rd] = __ldcg(&g_U2[b * 768 + item]);
        item = t + 512; rd = item >> 5; jx = item & 31;
        sU2[jx * 25 + rd] = __ldcg(&g_U2[b * 768 + item]);
    }
    if (t < 96) {
        int rd = t >> 2, il = t & 3;
        sPU1[il * 24 + rd] = __ldcg(&g_PU1[(b * RD + rd) * 32 + ig * 4 + il]);
    }
    __syncthreads();

    // ---- main loop: 16 kk per half ----
    u64 acc[12];
    if (half == 0) {
#pragma unroll
        for (int rdp = 0; rdp < 12; rdp++) {
            float lo = sPU1[i_loc * 24 + 2 * rdp]     * sU2[j * 25 + 2 * rdp];
            float hi = sPU1[i_loc * 24 + 2 * rdp + 1] * sU2[j * 25 + 2 * rdp + 1];
            acc[rdp] = pk2(lo, hi);
        }
    } else {
        u64 one = pk2(1.0f, 1.0f);
#pragma unroll
        for (int rdp = 0; rdp < 12; rdp++) acc[rdp] = one;
    }

    const uint32_t sb = smem_u32(sBW) + (uint32_t)(half * 16 * 12 * 16);
#pragma unroll
    for (int kl = 0; kl < 16; kl++) {
        u64 xx = pk2(xs[kl], xs[kl]);
#pragma unroll
        for (int rdp = 0; rdp < 12; rdp++) {
            u64 w, c;
            lds_wc(w, c, sb + (uint32_t)((kl * 12 + rdp) * 16));
            acc[rdp] = mul2(acc[rdp], fma2(xx, w, c));
        }
    }

    // ---- exchange: half1 -> shared ----
    if (half == 1) {
        u64* dst = sAcc + ((size_t)i_loc * 32 + jj) * 12;
#pragma unroll
        for (int rdp = 0; rdp < 12; rdp++) dst[rdp] = acc[rdp];
    }
    __syncthreads();

    if (half == 0) {
        const u64* src = sAcc + ((size_t)i_loc * 32 + jj) * 12;
        float tv[24];
#pragma unroll
        for (int rdp = 0; rdp < 12; rdp++) {
            u64 mm = mul2(acc[rdp], src[rdp]);
            float lo, hi;
            upk2(mm, lo, hi);
            tv[2 * rdp]     = 1.0f - lo;
            tv[2 * rdp + 1] = 1.0f - hi;
        }
        float pr0 = 1.0f, pr1 = 1.0f, pr2 = 1.0f;
#pragma unroll
        for (int d = 0; d < 8; d++) {
            pr0 *= tv[d];
            pr1 *= tv[8 + d];
            pr2 *= tv[16 + d];
        }

        // binary output row (channels 0..14 copy, channel 15 merged)
        if (active) {
            float4 o[4];
#pragma unroll
            for (int q = 0; q < 4; q++) {
                o[q].x = xs[4 * q + 0]; o[q].y = xs[4 * q + 1];
                o[q].z = xs[4 * q + 2]; o[q].w = xs[4 * q + 3];
            }
            o[3].w = 1.0f - (1.0f - xs[15]) * pr2;
            float4* ob = (float4*)(out + (size_t)b * 16912 + 1040 + (size_t)(i * 31 + jj) * 16);
#pragma unroll
            for (int q = 0; q < 4; q++) ob[q] = o[q];
        } else {
            pr0 = 1.0f;
            pr1 = 1.0f;
        }

        float r0 = pr0, r1 = pr1;
#pragma unroll
        for (int s = 16; s > 0; s >>= 1) {
            r0 *= __shfl_xor_sync(0xFFFFFFFFu, r0, s);
            r1 *= __shfl_xor_sync(0xFFFFFFFFu, r1, s);
        }

        float uv = (lane < 31) ? uk : (1.0f - (1.0f - uk) * r1);
        out[(size_t)b * 16912 + 16 + i * 32 + lane] = uv;

        if (lane == 0) sWarpR0[i_loc] = r0;
    }
    __syncthreads();

    // ---- last-block nullary epilogue (tickets over 256 main blocks) ----
    if (t == 0) {
        float p = sWarpR0[0] * sWarpR0[1] * sWarpR0[2] * sWarpR0[3];
        __stcg(&g_partB[b * 8 + ig], p);
        __threadfence();
        unsigned int ticket = atomicAdd(&g_ctr, 1u);
        *sIsLast = (ticket == 255u) ? 1 : 0;
    }
    __syncthreads();

    if (*sIsLast) {
        __threadfence();
        if (t < 32) {
            int bb = t;
            float p = 1.0f;
#pragma unroll
            for (int g = 0; g < 8; g++) p *= __ldcg(&g_partB[bb * 8 + g]);
            float v = nul[bb * 16 + 15];
            out[(size_t)bb * 16912 + 15] = 1.0f - (1.0f - v) * p;
            __stcg(&g_flag[bb], 0u);     // reset flags for next replay
        }
        if (t == 0) atomicExch(&g_ctr, 0u);
    }
}

// ============================================================================
extern "C" void kernel_launch(void* const* d_in, const int* in_sizes, int n_in,
                              void* d_out, int out_size) {
    // Identify the 5 inputs by rank order of element count (all distinct):
    //   ork (24) < nul (512) < andk (8064) < una (32768) < binp (507904)
    int order[5] = {0, 1, 2, 3, 4};
    for (int a = 1; a < 5 && a < n_in; a++) {
        int key = order[a];
        int ks = in_sizes[key];
        int bpos = a - 1;
        while (bpos >= 0 && in_sizes[order[bpos]] > ks) {
            order[bpos + 1] = order[bpos];
            bpos--;
        }
        order[bpos + 1] = key;
    }
    const float* ork  = (const float*)d_in[order[0]];
    const float* nul  = (const float*)d_in[order[1]];
    const float* andk = (const float*)d_in[order[2]];
    const float* una  = (const float*)d_in[order[3]];
    const float* binp = (const float*)d_in[order[4]];
    float* out = (float*)d_out;

    kAll<<<288, 256>>>(nul, una, binp, andk, ork, out);
}

// round 10
// speedup vs baseline: 1.1733x; 1.1467x over previous
#include <cuda_runtime.h>
#include <cstdint>

// Problem constants:
// B=32, N=32, P0=16, P1=32, P2=16, R=3, D=8, V=2
// num_in = 112, RD = 24
// out per b: 16 (null) + 1024 (unary) + 32*31*16 (binary) = 16912

#define RD 24
#define NUMIN 112

typedef unsigned long long u64;

// -------- device scratch --------
__device__ float g_partB[32 * 4];          // per (b, ig) partial nullary product
__device__ unsigned int g_ctr = 0;         // last-block ticket counter

// -------- packed f32x2 helpers (Blackwell) --------
__device__ __forceinline__ u64 pk2(float a, float b) {
    u64 r; asm("mov.b64 %0, {%1,%2};" : "=l"(r) : "f"(a), "f"(b)); return r;
}
__device__ __forceinline__ void upk2(u64 v, float& a, float& b) {
    asm("mov.b64 {%0,%1}, %2;" : "=f"(a), "=f"(b) : "l"(v));
}
__device__ __forceinline__ u64 fma2(u64 a, u64 b, u64 c) {
    u64 d; asm("fma.rn.f32x2 %0, %1, %2, %3;" : "=l"(d) : "l"(a), "l"(b), "l"(c)); return d;
}
__device__ __forceinline__ u64 mul2(u64 a, u64 b) {
    u64 d; asm("mul.rn.f32x2 %0, %1, %2;" : "=l"(d) : "l"(a), "l"(b)); return d;
}
__device__ __forceinline__ void lds_wc(u64& w, u64& c, uint32_t addr) {
    asm volatile("ld.shared.v2.u64 {%0,%1}, [%2];" : "=l"(w), "=l"(c) : "r"(addr));
}
__device__ __forceinline__ uint32_t smem_u32(const void* p) {
    uint32_t a;
    asm("{ .reg .u64 t; cvta.to.shared.u64 t, %1; cvt.u32.u64 %0, t; }" : "=r"(a) : "l"(p));
    return a;
}

// ============================================================================
// Fused kernel: grid = (4 ig, 32 b), block = 256 (8 warps).
// Warp w: pair p = w&3 -> rows i0 = ig*8+2p, i1 = i0+1; half = w>>2 (kk range).
// Each thread processes TWO i-rows, sharing every weight LDS.128 between them.
// ============================================================================
__global__ __launch_bounds__(256, 1)
void kFused(const float* __restrict__ nul, const float* __restrict__ una,
            const float* __restrict__ binp, const float* __restrict__ andk,
            const float* __restrict__ ork, float* __restrict__ out) {
    // regA: prologue sWC(21504)+sU(4096); after prologue reused as sAcc(25600)
    __shared__ __align__(16) char regA[25600];
    float2* sWC  = (float2*)regA;             // [RD*NUMIN] (w,c)
    float*  sU   = (float*)(regA + 21504);    // [32*32] unary transposed [k][i]
    u64*    sAcc = (u64*)regA;                // [(pair*32+jj)*25 + slot]

    __shared__ float4 sBW[384];               // packed binary weights [kk][rdp]
    __shared__ float  sU2[32 * 25];           // U2[j][rd], stride 25
    __shared__ float  sPU1[8 * 24];           // PN*U1*ok for local 8 i's
    __shared__ float  sN[16];
    __shared__ float  sOK[24];
    __shared__ float  sWarpR0[8];
    __shared__ int    sIsLast;

    const int ig   = blockIdx.x;              // 0..3
    const int b    = blockIdx.y;              // 0..31
    const int t    = threadIdx.x;             // 0..255
    const int wid  = t >> 5;                  // 0..7
    const int lane = t & 31;
    const int pair = wid & 3;                 // 0..3
    const int half = wid >> 2;                // 0 or 1
    const int i0   = ig * 8 + 2 * pair;
    const int i1   = i0 + 1;

    const int  jj     = lane;
    const bool active = (jj < 31);
    const int  jj_s   = active ? jj : 0;
    const int  j0     = jj_s + (jj_s >= i0);
    const int  ip0    = i0 - (jj_s < i0);
    const int  j1     = jj_s + (jj_s >= i1);
    const int  ip1    = i1 - (jj_s < i1);

    // ---- hoisted global loads: this half's 16 x-values for BOTH rows ----
    float xs0[16], xs1[16];
    {
        const size_t r0 = half ? (((size_t)b * 32 + j0) * 31 + ip0)
                               : (((size_t)b * 32 + i0) * 31 + jj_s);
        const size_t r1 = half ? (((size_t)b * 32 + j1) * 31 + ip1)
                               : (((size_t)b * 32 + i1) * 31 + jj_s);
        const float4* p0 = (const float4*)(binp + r0 * 16);
        const float4* p1 = (const float4*)(binp + r1 * 16);
        float4 v0[4], v1[4];
#pragma unroll
        for (int q = 0; q < 4; q++) v0[q] = p0[q];
#pragma unroll
        for (int q = 0; q < 4; q++) v1[q] = p1[q];
#pragma unroll
        for (int q = 0; q < 4; q++) {
            xs0[4 * q + 0] = v0[q].x; xs0[4 * q + 1] = v0[q].y;
            xs0[4 * q + 2] = v0[q].z; xs0[4 * q + 3] = v0[q].w;
            xs1[4 * q + 0] = v1[q].x; xs1[4 * q + 1] = v1[q].y;
            xs1[4 * q + 2] = v1[q].z; xs1[4 * q + 3] = v1[q].w;
        }
    }
    float uk0 = 0.0f, uk1 = 0.0f;
    if (half == 0) {
        uk0 = una[(size_t)b * 1024 + i0 * 32 + lane];
        uk1 = una[(size_t)b * 1024 + i1 * 32 + lane];
    }

    // ---- phase 1: softmax weights (fast math) + staging (stride 256) ----
    for (int idx = t; idx < RD * NUMIN; idx += 256) {
        float a0 = andk[idx * 3 + 0];
        float a1 = andk[idx * 3 + 1];
        float a2 = andk[idx * 3 + 2];
        float e0 = __expf(a0), e1 = __expf(a1), e2 = __expf(a2);
        float inv = __fdividef(1.0f, e0 + e1 + e2);
        sWC[idx] = make_float2((e0 - e1) * inv, (e1 + e2) * inv);
    }
    for (int idx = t; idx < 1024; idx += 256) {
        int ii = idx >> 5, k = idx & 31;
        sU[k * 32 + ii] = una[b * 1024 + idx];
    }
    if (t < 16) sN[t] = nul[b * 16 + t];
    else if (t >= 32 && t < 56) {
        float x = ork[t - 32];
        sOK[t - 32] = __fdividef(1.0f, 1.0f + __expf(-x));
    }
    __syncthreads();

    // ---- phase 2a: packed binary weights (384 entries, stride 256) ----
    for (int idx = t; idx < 384; idx += 256) {
        int kk = idx / 12, rdp = idx % 12;
        int slice = (kk < 16) ? (80 + kk) : (96 + kk - 16);
        float2 lo = sWC[(2 * rdp)     * NUMIN + slice];
        float2 hi = sWC[(2 * rdp + 1) * NUMIN + slice];
        sBW[idx] = make_float4(lo.x, hi.x, lo.y, hi.y);
    }
    // ---- phase 2b: U2 for all (j, rd), 768 items, 4-way split chains ----
    for (int item = t; item < 768; item += 256) {
        int jx = item & 31, rd = item >> 5;
        const float2* wc = sWC + rd * NUMIN + 48;
        float pa = 1.0f, pb = 1.0f, pc = 1.0f, pd = 1.0f;
#pragma unroll
        for (int k = 0; k < 8; k++) {
            float2 w0 = wc[k],      w1 = wc[8 + k];
            float2 w2 = wc[16 + k], w3 = wc[24 + k];
            pa *= fmaf(sU[k * 32 + jx],        w0.x, w0.y);
            pb *= fmaf(sU[(8 + k) * 32 + jx],  w1.x, w1.y);
            pc *= fmaf(sU[(16 + k) * 32 + jx], w2.x, w2.y);
            pd *= fmaf(sU[(24 + k) * 32 + jx], w3.x, w3.y);
        }
        sU2[jx * 25 + rd] = (pa * pb) * (pc * pd);
    }
    // ---- phase 2c: PU1 for local 8 i's (192 items) ----
    if (t < 192) {
        int il = t & 7, rd = t >> 3;
        int ii = ig * 8 + il;
        const float2* wc = sWC + rd * NUMIN;
        float pa = 1.0f, pb = 1.0f, pc = 1.0f, pd = 1.0f;
#pragma unroll
        for (int k = 0; k < 8; k++) {
            float2 w0 = wc[k], w1 = wc[8 + k];
            pa *= fmaf(sN[k],     w0.x, w0.y);
            pb *= fmaf(sN[8 + k], w1.x, w1.y);
        }
#pragma unroll
        for (int k = 0; k < 16; k++) {
            float2 w0 = wc[16 + k], w1 = wc[32 + k];
            pc *= fmaf(sU[k * 32 + ii],        w0.x, w0.y);
            pd *= fmaf(sU[(16 + k) * 32 + ii], w1.x, w1.y);
        }
        sPU1[il * 24 + rd] = ((pa * pb) * (pc * pd)) * sOK[rd];
    }
    __syncthreads();

    // ---- init accumulators ----
    u64 acc0[12], acc1[12];
    if (half == 0) {
#pragma unroll
        for (int rdp = 0; rdp < 12; rdp++) {
            float lo0 = sPU1[(2 * pair) * 24 + 2 * rdp]         * sU2[j0 * 25 + 2 * rdp];
            float hi0 = sPU1[(2 * pair) * 24 + 2 * rdp + 1]     * sU2[j0 * 25 + 2 * rdp + 1];
            float lo1 = sPU1[(2 * pair + 1) * 24 + 2 * rdp]     * sU2[j1 * 25 + 2 * rdp];
            float hi1 = sPU1[(2 * pair + 1) * 24 + 2 * rdp + 1] * sU2[j1 * 25 + 2 * rdp + 1];
            acc0[rdp] = pk2(lo0, hi0);
            acc1[rdp] = pk2(lo1, hi1);
        }
    } else {
        u64 one = pk2(1.0f, 1.0f);
#pragma unroll
        for (int rdp = 0; rdp < 12; rdp++) { acc0[rdp] = one; acc1[rdp] = one; }
    }

    // ---- main loop: 16 kk, each weight LDS.128 shared between both rows ----
    const uint32_t sb = smem_u32(sBW) + (uint32_t)(half * 16 * 12 * 16);
#pragma unroll
    for (int kl = 0; kl < 16; kl++) {
        u64 xx0 = pk2(xs0[kl], xs0[kl]);
        u64 xx1 = pk2(xs1[kl], xs1[kl]);
#pragma unroll
        for (int rdp = 0; rdp < 12; rdp++) {
            u64 w, c;
            lds_wc(w, c, sb + (uint32_t)((kl * 12 + rdp) * 16));
            acc0[rdp] = mul2(acc0[rdp], fma2(xx0, w, c));
            acc1[rdp] = mul2(acc1[rdp], fma2(xx1, w, c));
        }
    }

    // ---- exchange: half1 -> sAcc (reuses regA; prologue reads are done) ----
    __syncthreads();   // all phase-2 readers of sWC/sU have passed (post-phase2 barrier)
    if (half == 1) {
        u64* dst = sAcc + ((size_t)(pair * 32 + jj)) * 25;
#pragma unroll
        for (int rdp = 0; rdp < 12; rdp++) { dst[rdp] = acc0[rdp]; dst[12 + rdp] = acc1[rdp]; }
    }
    __syncthreads();

    if (half == 0) {
        const u64* src = sAcc + ((size_t)(pair * 32 + jj)) * 25;
        float tv0[24], tv1[24];
#pragma unroll
        for (int rdp = 0; rdp < 12; rdp++) {
            u64 m0 = mul2(acc0[rdp], src[rdp]);
            u64 m1 = mul2(acc1[rdp], src[12 + rdp]);
            float lo, hi;
            upk2(m0, lo, hi);
            tv0[2 * rdp] = 1.0f - lo; tv0[2 * rdp + 1] = 1.0f - hi;
            upk2(m1, lo, hi);
            tv1[2 * rdp] = 1.0f - lo; tv1[2 * rdp + 1] = 1.0f - hi;
        }
        float pr00 = 1.0f, pr01 = 1.0f, pr02 = 1.0f;
        float pr10 = 1.0f, pr11 = 1.0f, pr12 = 1.0f;
#pragma unroll
        for (int d = 0; d < 8; d++) {
            pr00 *= tv0[d]; pr01 *= tv0[8 + d]; pr02 *= tv0[16 + d];
            pr10 *= tv1[d]; pr11 *= tv1[8 + d]; pr12 *= tv1[16 + d];
        }

        // binary output rows (channels 0..14 copy, channel 15 merged)
        if (active) {
            float4 o[4];
#pragma unroll
            for (int q = 0; q < 4; q++) {
                o[q].x = xs0[4 * q + 0]; o[q].y = xs0[4 * q + 1];
                o[q].z = xs0[4 * q + 2]; o[q].w = xs0[4 * q + 3];
            }
            o[3].w = 1.0f - (1.0f - xs0[15]) * pr02;
            float4* ob = (float4*)(out + (size_t)b * 16912 + 1040 + (size_t)(i0 * 31 + jj) * 16);
#pragma unroll
            for (int q = 0; q < 4; q++) ob[q] = o[q];
#pragma unroll
            for (int q = 0; q < 4; q++) {
                o[q].x = xs1[4 * q + 0]; o[q].y = xs1[4 * q + 1];
                o[q].z = xs1[4 * q + 2]; o[q].w = xs1[4 * q + 3];
            }
            o[3].w = 1.0f - (1.0f - xs1[15]) * pr12;
            ob = (float4*)(out + (size_t)b * 16912 + 1040 + (size_t)(i1 * 31 + jj) * 16);
#pragma unroll
            for (int q = 0; q < 4; q++) ob[q] = o[q];
        } else {
            pr00 = 1.0f; pr01 = 1.0f;
            pr10 = 1.0f; pr11 = 1.0f;
        }

        // warp product-reductions over jj (both rows)
        float r00 = pr00, r01 = pr01, r10 = pr10, r11 = pr11;
#pragma unroll
        for (int s = 16; s > 0; s >>= 1) {
            r00 *= __shfl_xor_sync(0xFFFFFFFFu, r00, s);
            r01 *= __shfl_xor_sync(0xFFFFFFFFu, r01, s);
            r10 *= __shfl_xor_sync(0xFFFFFFFFu, r10, s);
            r11 *= __shfl_xor_sync(0xFFFFFFFFu, r11, s);
        }

        // unary output rows
        {
            float uv0 = (lane < 31) ? uk0 : (1.0f - (1.0f - uk0) * r01);
            float uv1 = (lane < 31) ? uk1 : (1.0f - (1.0f - uk1) * r11);
            out[(size_t)b * 16912 + 16 + i0 * 32 + lane] = uv0;
            out[(size_t)b * 16912 + 16 + i1 * 32 + lane] = uv1;
        }

        if (lane == 0) {
            sWarpR0[2 * pair]     = r00;
            sWarpR0[2 * pair + 1] = r10;
        }
    }
    __syncthreads();

    // ---- last-block nullary epilogue (128 blocks -> ticket 127) ----
    if (t == 0) {
        float p = 1.0f;
#pragma unroll
        for (int w = 0; w < 8; w++) p *= sWarpR0[w];
        __stcg(&g_partB[b * 4 + ig], p);
        __threadfence();
        unsigned int ticket = atomicAdd(&g_ctr, 1u);
        sIsLast = (ticket == 127u) ? 1 : 0;
    }
    __syncthreads();

    if (sIsLast) {
        __threadfence();
        for (int item = t; item < 512; item += 256) {
            int bb = item >> 4, c = item & 15;
            float v = nul[bb * 16 + c];
            if (c == 15) {
                float p = __ldcg(&g_partB[bb * 4 + 0]) * __ldcg(&g_partB[bb * 4 + 1]) *
                          __ldcg(&g_partB[bb * 4 + 2]) * __ldcg(&g_partB[bb * 4 + 3]);
                v = 1.0f - (1.0f - v) * p;
            }
            out[(size_t)bb * 16912 + c] = v;
        }
        if (t == 0) atomicExch(&g_ctr, 0u);
    }
}

// ============================================================================
extern "C" void kernel_launch(void* const* d_in, const int* in_sizes, int n_in,
                              void* d_out, int out_size) {
    // Identify the 5 inputs by rank order of element count (all distinct):
    //   ork (24) < nul (512) < andk (8064) < una (32768) < binp (507904)
    int order[5] = {0, 1, 2, 3, 4};
    for (int a = 1; a < 5 && a < n_in; a++) {
        int key = order[a];
        int ks = in_sizes[key];
        int bpos = a - 1;
        while (bpos >= 0 && in_sizes[order[bpos]] > ks) {
            order[bpos + 1] = order[bpos];
            bpos--;
        }
        order[bpos + 1] = key;
    }
    const float* ork  = (const float*)d_in[order[0]];
    const float* nul  = (const float*)d_in[order[1]];
    const float* andk = (const float*)d_in[order[2]];
    const float* una  = (const float*)d_in[order[3]];
    const float* binp = (const float*)d_in[order[4]];
    float* out = (float*)d_out;

    kFused<<<dim3(4, 32), 256>>>(nul, una, binp, andk, ork, out);
}

// round 11
// speedup vs baseline: 1.1961x; 1.0194x over previous
#include <cuda_runtime.h>
#include <cstdint>

// Problem constants:
// B=32, N=32, P0=16, P1=32, P2=16, R=3, D=8, V=2
// num_in = 112, RD = 24
// out per b: 16 (null) + 1024 (unary) + 32*31*16 (binary) = 16912

#define RD 24
#define NUMIN 112

typedef unsigned long long u64;

// -------- device scratch --------
__device__ float g_partB[32 * 4];          // per (b, ig) partial nullary product
__device__ unsigned int g_ctr = 0;         // last-block ticket counter

// -------- packed f32x2 helpers (Blackwell) --------
__device__ __forceinline__ u64 pk2(float a, float b) {
    u64 r; asm("mov.b64 %0, {%1,%2};" : "=l"(r) : "f"(a), "f"(b)); return r;
}
__device__ __forceinline__ void upk2(u64 v, float& a, float& b) {
    asm("mov.b64 {%0,%1}, %2;" : "=f"(a), "=f"(b) : "l"(v));
}
__device__ __forceinline__ u64 fma2(u64 a, u64 b, u64 c) {
    u64 d; asm("fma.rn.f32x2 %0, %1, %2, %3;" : "=l"(d) : "l"(a), "l"(b), "l"(c)); return d;
}
__device__ __forceinline__ u64 mul2(u64 a, u64 b) {
    u64 d; asm("mul.rn.f32x2 %0, %1, %2;" : "=l"(d) : "l"(a), "l"(b)); return d;
}
__device__ __forceinline__ void lds_wc(u64& w, u64& c, uint32_t addr) {
    asm volatile("ld.shared.v2.u64 {%0,%1}, [%2];" : "=l"(w), "=l"(c) : "r"(addr));
}
__device__ __forceinline__ uint32_t smem_u32(const void* p) {
    uint32_t a;
    asm("{ .reg .u64 t; cvta.to.shared.u64 t, %1; cvt.u32.u64 %0, t; }" : "=r"(a) : "l"(p));
    return a;
}

// ============================================================================
// Fused kernel: grid = (4 ig, 32 b), block = 512 (wid 0..15).
// half = wid>>3, i_loc = wid&7, lane = jj.
// Phase A (pre-main): direct sBW softmax only (~800-cycle critical path).
// Main loop: 16 kk per half, accs start at 1.
// Phase B (post-main): full softmax slices 0..79, U2/PU1 chains, combine.
// ============================================================================
__global__ __launch_bounds__(512, 1)
void kFused(const float* __restrict__ nul, const float* __restrict__ una,
            const float* __restrict__ binp, const float* __restrict__ andk,
            const float* __restrict__ ork, float* __restrict__ out) {
    // regA union:
    //   phase B:  sWC2 [24][80] float2 (15360 B) | sU [32][32] float (4096 B)
    //   exchange: sAcc 8*32*12 u64 (24576 B)   — written only after bar3
    __shared__ __align__(16) char regA[24576];
    float2* sWC2 = (float2*)regA;             // [rd*80 + k], k in 0..79
    float*  sU   = (float*)(regA + 15360);    // [k][i] unary transposed
    u64*    sAcc = (u64*)regA;

    __shared__ float4 sBW[384];               // packed binary weights [kk][rdp]
    __shared__ float  sU2[32 * 25];           // U2[j][rd], stride 25
    __shared__ float  sPU1[8 * 24];           // PN*U1*ok for local 8 i's
    __shared__ float  sN[16];
    __shared__ float  sOK[24];
    __shared__ float  sWarpR0[8];
    __shared__ int    sIsLast;

    const int ig   = blockIdx.x;              // 0..3
    const int b    = blockIdx.y;              // 0..31
    const int t    = threadIdx.x;             // 0..511
    const int wid  = t >> 5;                  // 0..15
    const int lane = t & 31;
    const int half  = wid >> 3;               // 0 or 1
    const int i_loc = wid & 7;
    const int i     = ig * 8 + i_loc;

    const int  jj     = lane;
    const bool active = (jj < 31);
    const int  jj_s   = active ? jj : 0;
    const int  j      = jj_s + (jj_s >= i);   // second object index
    const int  ip     = i - (jj_s < i);       // binary col index for (j,i)

    // ---- hoisted global loads: this half's 16 x-values ----
    float xs[16];
    {
        const size_t row = half ? (((size_t)b * 32 + j) * 31 + ip)
                                : (((size_t)b * 32 + i) * 31 + jj_s);
        const float4* p = (const float4*)(binp + row * 16);
        float4 v[4];
#pragma unroll
        for (int q = 0; q < 4; q++) v[q] = p[q];
#pragma unroll
        for (int q = 0; q < 4; q++) {
            xs[4 * q + 0] = v[q].x; xs[4 * q + 1] = v[q].y;
            xs[4 * q + 2] = v[q].z; xs[4 * q + 3] = v[q].w;
        }
    }
    const float uk = (half == 0) ? una[(size_t)b * 1024 + i * 32 + lane] : 0.0f;

    // ---- Phase A: direct binary-weight softmax (threads 0..383) ----
    if (t < 384) {
        int kk = t / 12, rdp = t % 12;
        int slice = (kk < 16) ? (80 + kk) : (96 + kk - 16);
        const float* p0 = andk + ((size_t)((2 * rdp)     * NUMIN + slice)) * 3;
        const float* p1 = andk + ((size_t)((2 * rdp + 1) * NUMIN + slice)) * 3;
        float a0 = __ldg(p0), a1 = __ldg(p0 + 1), a2 = __ldg(p0 + 2);
        float b0 = __ldg(p1), b1 = __ldg(p1 + 1), b2 = __ldg(p1 + 2);
        float e0 = __expf(a0), e1 = __expf(a1), e2 = __expf(a2);
        float f0 = __expf(b0), f1 = __expf(b1), f2 = __expf(b2);
        float inva = __fdividef(1.0f, e0 + e1 + e2);
        float invb = __fdividef(1.0f, f0 + f1 + f2);
        sBW[t] = make_float4((e0 - e1) * inva, (f0 - f1) * invb,
                             (e1 + e2) * inva, (f1 + f2) * invb);
    }
    __syncthreads();   // bar1: sBW ready

    // ---- main loop: 16 kk per half, accs init to 1 ----
    u64 acc[12];
    {
        u64 one = pk2(1.0f, 1.0f);
#pragma unroll
        for (int rdp = 0; rdp < 12; rdp++) acc[rdp] = one;
    }
    const uint32_t sb = smem_u32(sBW) + (uint32_t)(half * 16 * 12 * 16);
#pragma unroll
    for (int kl = 0; kl < 16; kl++) {
        u64 xx = pk2(xs[kl], xs[kl]);
#pragma unroll
        for (int rdp = 0; rdp < 12; rdp++) {
            u64 w, c;
            lds_wc(w, c, sb + (uint32_t)((kl * 12 + rdp) * 16));
            acc[rdp] = mul2(acc[rdp], fma2(xx, w, c));
        }
    }

    // ---- Phase B1: softmax slices 0..79 -> sWC2 ; staging ----
    for (int idx = t; idx < 1920; idx += 512) {
        int rd = idx / 80, k = idx - rd * 80;
        const float* p = andk + ((size_t)(rd * NUMIN + k)) * 3;
        float a0 = __ldg(p), a1 = __ldg(p + 1), a2 = __ldg(p + 2);
        float e0 = __expf(a0), e1 = __expf(a1), e2 = __expf(a2);
        float inv = __fdividef(1.0f, e0 + e1 + e2);
        sWC2[idx] = make_float2((e0 - e1) * inv, (e1 + e2) * inv);
    }
    for (int idx = t; idx < 1024; idx += 512) {
        int ii = idx >> 5, k = idx & 31;
        sU[k * 32 + ii] = una[b * 1024 + idx];
    }
    if (t < 16) sN[t] = nul[b * 16 + t];
    else if (t >= 32 && t < 56) {
        float x = ork[t - 32];
        sOK[t - 32] = __fdividef(1.0f, 1.0f + __expf(-x));
    }
    __syncthreads();   // bar2: sWC2/sU/sN/sOK ready

    // ---- Phase B2: U2 (768 items) + PU1 (192 items) chains ----
    for (int item = t; item < 768; item += 512) {
        int jx = item & 31, rd = item >> 5;
        const float2* wc = sWC2 + rd * 80 + 48;
        float pa = 1.0f, pb = 1.0f, pc = 1.0f, pd = 1.0f;
#pragma unroll
        for (int k = 0; k < 8; k++) {
            float2 w0 = wc[k],      w1 = wc[8 + k];
            float2 w2 = wc[16 + k], w3 = wc[24 + k];
            pa *= fmaf(sU[k * 32 + jx],        w0.x, w0.y);
            pb *= fmaf(sU[(8 + k) * 32 + jx],  w1.x, w1.y);
            pc *= fmaf(sU[(16 + k) * 32 + jx], w2.x, w2.y);
            pd *= fmaf(sU[(24 + k) * 32 + jx], w3.x, w3.y);
        }
        sU2[jx * 25 + rd] = (pa * pb) * (pc * pd);
    }
    if (t < 192) {
        int il = t & 7, rd = t >> 3;
        int ii = ig * 8 + il;
        const float2* wc = sWC2 + rd * 80;
        float pa = 1.0f, pb = 1.0f, pc = 1.0f, pd = 1.0f;
#pragma unroll
        for (int k = 0; k < 8; k++) {
            float2 w0 = wc[k], w1 = wc[8 + k];
            pa *= fmaf(sN[k],     w0.x, w0.y);
            pb *= fmaf(sN[8 + k], w1.x, w1.y);
        }
#pragma unroll
        for (int k = 0; k < 16; k++) {
            float2 w0 = wc[16 + k], w1 = wc[32 + k];
            pc *= fmaf(sU[k * 32 + ii],        w0.x, w0.y);
            pd *= fmaf(sU[(16 + k) * 32 + ii], w1.x, w1.y);
        }
        sPU1[il * 24 + rd] = ((pa * pb) * (pc * pd)) * sOK[rd];
    }
    __syncthreads();   // bar3: sU2/sPU1 ready; all sWC2/sU reads done

    // ---- exchange: half1 -> sAcc (overwrites dead sWC2/sU region) ----
    if (half == 1) {
        u64* dst = sAcc + ((size_t)(i_loc * 32 + jj)) * 12;
#pragma unroll
        for (int rdp = 0; rdp < 12; rdp++) dst[rdp] = acc[rdp];
    }
    __syncthreads();   // bar4

    if (half == 0) {
        const u64* src = sAcc + ((size_t)(i_loc * 32 + jj)) * 12;
        float tv[24];
#pragma unroll
        for (int rdp = 0; rdp < 12; rdp++) {
            float pl = sPU1[i_loc * 24 + 2 * rdp]     * sU2[j * 25 + 2 * rdp];
            float ph = sPU1[i_loc * 24 + 2 * rdp + 1] * sU2[j * 25 + 2 * rdp + 1];
            u64 m = mul2(mul2(acc[rdp], src[rdp]), pk2(pl, ph));
            float lo, hi;
            upk2(m, lo, hi);
            tv[2 * rdp]     = 1.0f - lo;
            tv[2 * rdp + 1] = 1.0f - hi;
        }
        float pr0 = 1.0f, pr1 = 1.0f, pr2 = 1.0f;
#pragma unroll
        for (int d = 0; d < 8; d++) {
            pr0 *= tv[d];
            pr1 *= tv[8 + d];
            pr2 *= tv[16 + d];
        }

        // binary output row (channels 0..14 copy, channel 15 merged)
        if (active) {
            float4 o[4];
#pragma unroll
            for (int q = 0; q < 4; q++) {
                o[q].x = xs[4 * q + 0]; o[q].y = xs[4 * q + 1];
                o[q].z = xs[4 * q + 2]; o[q].w = xs[4 * q + 3];
            }
            o[3].w = 1.0f - (1.0f - xs[15]) * pr2;
            float4* ob = (float4*)(out + (size_t)b * 16912 + 1040 + (size_t)(i * 31 + jj) * 16);
#pragma unroll
            for (int q = 0; q < 4; q++) ob[q] = o[q];
        } else {
            pr0 = 1.0f;
            pr1 = 1.0f;
        }

        // warp product-reductions over jj
        float r0 = pr0, r1 = pr1;
#pragma unroll
        for (int s = 16; s > 0; s >>= 1) {
            r0 *= __shfl_xor_sync(0xFFFFFFFFu, r0, s);
            r1 *= __shfl_xor_sync(0xFFFFFFFFu, r1, s);
        }

        // unary output row
        float uv = (lane < 31) ? uk : (1.0f - (1.0f - uk) * r1);
        out[(size_t)b * 16912 + 16 + i * 32 + lane] = uv;

        if (lane == 0) sWarpR0[i_loc] = r0;
    }
    __syncthreads();

    // ---- last-block nullary epilogue (128 blocks -> ticket 127) ----
    if (t == 0) {
        float p = 1.0f;
#pragma unroll
        for (int w = 0; w < 8; w++) p *= sWarpR0[w];
        __stcg(&g_partB[b * 4 + ig], p);
        __threadfence();
        unsigned int ticket = atomicAdd(&g_ctr, 1u);
        sIsLast = (ticket == 127u) ? 1 : 0;
    }
    __syncthreads();

    if (sIsLast) {
        __threadfence();
        if (t < 512) {
            int bb = t >> 4, c = t & 15;
            float v = nul[bb * 16 + c];
            if (c == 15) {
                float p = __ldcg(&g_partB[bb * 4 + 0]) * __ldcg(&g_partB[bb * 4 + 1]) *
                          __ldcg(&g_partB[bb * 4 + 2]) * __ldcg(&g_partB[bb * 4 + 3]);
                v = 1.0f - (1.0f - v) * p;
            }
            out[(size_t)bb * 16912 + c] = v;
        }
        if (t == 0) atomicExch(&g_ctr, 0u);
    }
}

// ============================================================================
extern "C" void kernel_launch(void* const* d_in, const int* in_sizes, int n_in,
                              void* d_out, int out_size) {
    // Identify the 5 inputs by rank order of element count (all distinct):
    //   ork (24) < nul (512) < andk (8064) < una (32768) < binp (507904)
    int order[5] = {0, 1, 2, 3, 4};
    for (int a = 1; a < 5 && a < n_in; a++) {
        int key = order[a];
        int ks = in_sizes[key];
        int bpos = a - 1;
        while (bpos >= 0 && in_sizes[order[bpos]] > ks) {
            order[bpos + 1] = order[bpos];
            bpos--;
        }
        order[bpos + 1] = key;
    }
    const float* ork  = (const float*)d_in[order[0]];
    const float* nul  = (const float*)d_in[order[1]];
    const float* andk = (const float*)d_in[order[2]];
    const float* una  = (const float*)d_in[order[3]];
    const float* binp = (const float*)d_in[order[4]];
    float* out = (float*)d_out;

    kFused<<<dim3(4, 32), 512>>>(nul, una, binp, andk, ork, out);
}